// round 1
// baseline (speedup 1.0000x reference)
#include <cuda_runtime.h>
#include <math.h>
#include <stdint.h>

#define BATCH 4
#define SEQ   4096
#define DIM   1024
#define HEADS 16
#define DH    64
#define CHUNK 128
#define NCHUNK 32
#define BH    (BATCH*HEADS)
#define FEAT_SCALE 0.35355339059327373f  // 64^-0.25

// ---------------- scratch (device globals; no allocation allowed) ----------------
__device__ float g_qkv [BATCH*SEQ*3*DIM];     // 201 MB raw qkv
__device__ float g_qf  [BH*SEQ*DH];           // featurized q, [bh][n][64]
__device__ float g_kf  [BH*SEQ*DH];           // featurized k
__device__ float g_v   [BH*SEQ*DH];           // v transposed to [bh][n][64]
__device__ float g_attn[BATCH*SEQ*DIM];       // attention output [b][n][1024]
__device__ float g_kvch[BH*NCHUNK*DH*DH];     // per-chunk K^T V -> exclusive prefix
__device__ float g_ksch[BH*NCHUNK*DH];        // per-chunk sum(k) -> exclusive prefix

// ---------------- accurate sincos (immune to -use_fast_math) ----------------
__device__ __forceinline__ void rope_sincos(float ang, float& s, float& c) {
    double a  = (double)ang;                       // ang >= 0 always here
    double qd = floor(a * 0.63661977236758134 + 0.5);   // round(a / (pi/2))
    double r  = a - qd * 1.5707963267948966;
    float rf = (float)r;
    int qi = ((int)qd) & 3;
    float r2 = rf * rf;
    float sp = rf * (1.0f + r2 * (-1.6666667e-1f + r2 * (8.3333337e-3f
              + r2 * (-1.9841270e-4f + r2 * 2.7557319e-6f))));
    float cp = 1.0f + r2 * (-0.5f + r2 * (4.1666668e-2f
              + r2 * (-1.3888889e-3f + r2 * 2.4801587e-5f)));
    switch (qi) {
        case 0:  s =  sp; c =  cp; break;
        case 1:  s =  cp; c = -sp; break;
        case 2:  s = -sp; c = -cp; break;
        default: s = -cp; c =  sp; break;
    }
}

// ---------------- SGEMM: C[M,Nn] = A[M,K] @ B[K,Nn], all row-major ----------------
// BM=BN=128, BK=16, 256 threads, 8x8 register tile. All dims divisible by tiles.
__global__ void sgemm128(const float* __restrict__ A, const float* __restrict__ B,
                         float* __restrict__ C, int M, int Nn, int K) {
    __shared__ float As[16 * 132];   // [k][m], padded pitch 132
    __shared__ float Bs[16 * 128];   // [k][n]

    const int tid = threadIdx.x;
    const int bx = blockIdx.x;       // N tile
    const int by = blockIdx.y;       // M tile
    const int tx = tid & 15;         // 0..15 -> N
    const int ty = tid >> 4;         // 0..15 -> M

    const int aRow  = tid >> 2;           // 0..63
    const int aCol4 = (tid & 3) * 4;      // 0,4,8,12
    const int bRow  = tid >> 5;           // 0..7
    const int bCol4 = (tid & 31) * 4;     // 0..124

    const float* Ab = A + (size_t)(by * 128) * K;
    const float* Bb = B + (size_t)(bx * 128);

    float acc[8][8];
#pragma unroll
    for (int i = 0; i < 8; i++)
#pragma unroll
        for (int j = 0; j < 8; j++) acc[i][j] = 0.0f;

    for (int k0 = 0; k0 < K; k0 += 16) {
#pragma unroll
        for (int r = 0; r < 2; r++) {
            float4 a = *(const float4*)(Ab + (size_t)(aRow + 64 * r) * K + k0 + aCol4);
            As[(aCol4 + 0) * 132 + aRow + 64 * r] = a.x;
            As[(aCol4 + 1) * 132 + aRow + 64 * r] = a.y;
            As[(aCol4 + 2) * 132 + aRow + 64 * r] = a.z;
            As[(aCol4 + 3) * 132 + aRow + 64 * r] = a.w;
        }
#pragma unroll
        for (int r = 0; r < 2; r++) {
            float4 b = *(const float4*)(Bb + (size_t)(k0 + bRow + 8 * r) * Nn + bCol4);
            *(float4*)&Bs[(bRow + 8 * r) * 128 + bCol4] = b;
        }
        __syncthreads();
#pragma unroll
        for (int kk = 0; kk < 16; kk++) {
            float ra[8], rb[8];
            *(float4*)&ra[0] = *(const float4*)&As[kk * 132 + ty * 8];
            *(float4*)&ra[4] = *(const float4*)&As[kk * 132 + ty * 8 + 4];
            *(float4*)&rb[0] = *(const float4*)&Bs[kk * 128 + tx * 8];
            *(float4*)&rb[4] = *(const float4*)&Bs[kk * 128 + tx * 8 + 4];
#pragma unroll
            for (int i = 0; i < 8; i++)
#pragma unroll
                for (int j = 0; j < 8; j++) acc[i][j] += ra[i] * rb[j];
        }
        __syncthreads();
    }

    float* Cb = C + (size_t)(by * 128 + ty * 8) * Nn + bx * 128 + tx * 8;
#pragma unroll
    for (int i = 0; i < 8; i++) {
        *(float4*)&Cb[(size_t)i * Nn + 0] = make_float4(acc[i][0], acc[i][1], acc[i][2], acc[i][3]);
        *(float4*)&Cb[(size_t)i * Nn + 4] = make_float4(acc[i][4], acc[i][5], acc[i][6], acc[i][7]);
    }
}

// ---------------- featurize: RoPE + elu(x*s)+1, transpose to [bh][n][64] ----------------
__global__ void featurize_kernel(const float* __restrict__ qkv,
                                 float* __restrict__ qf, float* __restrict__ kf,
                                 float* __restrict__ v) {
    int idx = blockIdx.x * blockDim.x + threadIdx.x;   // BATCH*SEQ*HEADS*32 threads
    int d = idx & 31;
    int h = (idx >> 5) & 15;
    int n = (idx >> 9) & 4095;
    int b = idx >> 21;

    size_t base = ((size_t)(b * SEQ + n)) * (3 * DIM);
    int col = h * 64 + d;
    float q1 = qkv[base + col],            q2 = qkv[base + col + 32];
    float k1 = qkv[base + DIM + col],      k2 = qkv[base + DIM + col + 32];
    float v1 = qkv[base + 2 * DIM + col],  v2 = qkv[base + 2 * DIM + col + 32];

    // inv_freq = 10000^(-d/32), computed in double then rounded (matches fp32 ref to ~ulp)
    float inv_f = (float)exp(-(double)d * (9.210340371976184 / 32.0));
    float ang = (float)n * inv_f;          // fp32 product like the reference
    float s, c;
    rope_sincos(ang, s, c);

    float qr1 = q1 * c - q2 * s, qr2 = q1 * s + q2 * c;
    float kr1 = k1 * c - k2 * s, kr2 = k1 * s + k2 * c;

    float yq1 = qr1 * FEAT_SCALE, yq2 = qr2 * FEAT_SCALE;
    float yk1 = kr1 * FEAT_SCALE, yk2 = kr2 * FEAT_SCALE;
    float fq1 = (yq1 > 0.0f) ? yq1 + 1.0f : expf(yq1);
    float fq2 = (yq2 > 0.0f) ? yq2 + 1.0f : expf(yq2);
    float fk1 = (yk1 > 0.0f) ? yk1 + 1.0f : expf(yk1);
    float fk2 = (yk2 > 0.0f) ? yk2 + 1.0f : expf(yk2);

    size_t obase = (((size_t)(b * HEADS + h)) * SEQ + n) * DH + d;
    qf[obase] = fq1; qf[obase + 32] = fq2;
    kf[obase] = fk1; kf[obase + 32] = fk2;
    v [obase] = v1;  v [obase + 32] = v2;
}

// ---------------- pass A: per-chunk K^T V (64x64) and sum(k) ----------------
__global__ void chunk_sums_kernel(const float* __restrict__ kf, const float* __restrict__ v,
                                  float* __restrict__ kvch, float* __restrict__ ksch) {
    extern __shared__ float sm[];
    float* Ks = sm;            // [128][64]
    float* Vs = sm + 8192;     // [128][64]

    int blk = blockIdx.x;
    int c  = blk % NCHUNK;
    int bh = blk / NCHUNK;
    int tid = threadIdx.x;

    size_t gbase = (((size_t)bh) * SEQ + (size_t)c * CHUNK) * DH;  // contiguous 8192 floats
    for (int i = tid; i < 2048; i += 256) {
        ((float4*)Ks)[i] = ((const float4*)(kf + gbase))[i];
        ((float4*)Vs)[i] = ((const float4*)(v  + gbase))[i];
    }
    __syncthreads();

    int i0 = (tid >> 4) * 4;   // K-dim rows of output
    int j0 = (tid & 15) * 4;   // V-dim cols
    float acc[4][4];
#pragma unroll
    for (int i = 0; i < 4; i++)
#pragma unroll
        for (int j = 0; j < 4; j++) acc[i][j] = 0.0f;

    for (int r = 0; r < CHUNK; r++) {
        float4 kv = *(const float4*)&Ks[r * 64 + i0];
        float4 vv = *(const float4*)&Vs[r * 64 + j0];
        float ka[4] = {kv.x, kv.y, kv.z, kv.w};
        float va[4] = {vv.x, vv.y, vv.z, vv.w};
#pragma unroll
        for (int i = 0; i < 4; i++)
#pragma unroll
            for (int j = 0; j < 4; j++) acc[i][j] += ka[i] * va[j];
    }

    size_t obase = ((size_t)bh * NCHUNK + c) * (DH * DH);
#pragma unroll
    for (int i = 0; i < 4; i++)
        *(float4*)&kvch[obase + (size_t)(i0 + i) * 64 + j0] =
            make_float4(acc[i][0], acc[i][1], acc[i][2], acc[i][3]);

    if (tid < 64) {
        float ssum = 0.0f;
        for (int r = 0; r < CHUNK; r++) ssum += Ks[r * 64 + tid];
        ksch[((size_t)bh * NCHUNK + c) * DH + tid] = ssum;
    }
}

// ---------------- pass B: exclusive prefix over chunks (in place) ----------------
__global__ void prefix_kernel(float* __restrict__ kvch, float* __restrict__ ksch) {
    int bh = blockIdx.x;
    for (int e = threadIdx.x; e < DH * DH; e += blockDim.x) {
        float acc = 0.0f;
        for (int c = 0; c < NCHUNK; c++) {
            float* p = &kvch[((size_t)bh * NCHUNK + c) * (DH * DH) + e];
            float t = *p; *p = acc; acc += t;
        }
    }
    for (int e = threadIdx.x; e < DH; e += blockDim.x) {
        float acc = 0.0f;
        for (int c = 0; c < NCHUNK; c++) {
            float* p = &ksch[((size_t)bh * NCHUNK + c) * DH + e];
            float t = *p; *p = acc; acc += t;
        }
    }
}

// ---------------- pass C: per-chunk output ----------------
// out = tril(Q K^T) V + Q KVprev ; denom = rowsum(tril(QK^T)) + Q . KSprev
__global__ void chunk_out_kernel(const float* __restrict__ qf, const float* __restrict__ kf,
                                 const float* __restrict__ v, const float* __restrict__ kvch,
                                 const float* __restrict__ ksch, float* __restrict__ attn) {
    extern __shared__ float sm[];
    float* Qs   = sm;                       // [128][64]           8192
    float* KsT  = Qs + 8192;                // [64][128] pitch 132 8448
    float* Vs   = KsT + 8448;               // [128][64]           8192
    float* Ss   = Vs + 8192;                // [128][128]          16384
    float* KVp  = Ss + 16384;               // [64][64]            4096
    float* KSp  = KVp + 4096;               // [64]
    float* den  = KSp + 64;                 // [128]
    float* denp = den + 128;                // [128][16]           2048

    int blk = blockIdx.x;
    int c  = blk % NCHUNK;
    int bh = blk / NCHUNK;
    int b  = bh / HEADS;
    int h  = bh % HEADS;
    int tid = threadIdx.x;

    size_t gbase = (((size_t)bh) * SEQ + (size_t)c * CHUNK) * DH;
    for (int i = tid; i < 2048; i += 256) {
        ((float4*)Qs)[i] = ((const float4*)(qf + gbase))[i];
        ((float4*)Vs)[i] = ((const float4*)(v  + gbase))[i];
        float4 kq = ((const float4*)(kf + gbase))[i];
        int r  = i >> 4;          // row 0..127
        int c4 = (i & 15) * 4;    // col 0..60
        KsT[(c4 + 0) * 132 + r] = kq.x;
        KsT[(c4 + 1) * 132 + r] = kq.y;
        KsT[(c4 + 2) * 132 + r] = kq.z;
        KsT[(c4 + 3) * 132 + r] = kq.w;
    }
    {
        size_t kvbase = ((size_t)bh * NCHUNK + c) * (DH * DH);
        for (int i = tid; i < 1024; i += 256)
            ((float4*)KVp)[i] = ((const float4*)(kvch + kvbase))[i];
        if (tid < 64)
            KSp[tid] = ksch[((size_t)bh * NCHUNK + c) * DH + tid];
    }
    __syncthreads();

    // ---- stage 1: S = tril(Q K^T), plus per-thread row partial sums ----
    int ti = tid >> 4, tj = tid & 15;
    int t0 = ti * 8, s0 = tj * 8;
    {
        float acc[8][8];
#pragma unroll
        for (int i = 0; i < 8; i++)
#pragma unroll
            for (int j = 0; j < 8; j++) acc[i][j] = 0.0f;

        for (int dd = 0; dd < DH; dd++) {
            float ra[8], rb[8];
#pragma unroll
            for (int i = 0; i < 8; i++) ra[i] = Qs[(t0 + i) * 64 + dd];
            *(float4*)&rb[0] = *(const float4*)&KsT[dd * 132 + s0];
            *(float4*)&rb[4] = *(const float4*)&KsT[dd * 132 + s0 + 4];
#pragma unroll
            for (int i = 0; i < 8; i++)
#pragma unroll
                for (int j = 0; j < 8; j++) acc[i][j] += ra[i] * rb[j];
        }
#pragma unroll
        for (int i = 0; i < 8; i++) {
            float rsum = 0.0f;
#pragma unroll
            for (int j = 0; j < 8; j++) {
                float val = (s0 + j <= t0 + i) ? acc[i][j] : 0.0f;
                acc[i][j] = val;
                rsum += val;
            }
            denp[(t0 + i) * 16 + tj] = rsum;
            *(float4*)&Ss[(t0 + i) * 128 + s0]     = make_float4(acc[i][0], acc[i][1], acc[i][2], acc[i][3]);
            *(float4*)&Ss[(t0 + i) * 128 + s0 + 4] = make_float4(acc[i][4], acc[i][5], acc[i][6], acc[i][7]);
        }
    }
    __syncthreads();

    // ---- stage 2: denominators ----
    if (tid < 128) {
        float dsum = 0.0f;
#pragma unroll
        for (int j = 0; j < 16; j++) dsum += denp[tid * 16 + j];
        for (int dd = 0; dd < DH; dd++) dsum += Qs[tid * 64 + dd] * KSp[dd];
        den[tid] = fmaxf(dsum, 1e-6f);
    }
    __syncthreads();

    // ---- stage 3: out = S V + Q KVp, divide, store ----
    {
        int m0 = tj * 4;   // value dim cols (4 per thread), rows t0..t0+7
        float acc[8][4];
#pragma unroll
        for (int i = 0; i < 8; i++)
#pragma unroll
            for (int j = 0; j < 4; j++) acc[i][j] = 0.0f;

        for (int s = 0; s < CHUNK; s++) {
            float4 vv = *(const float4*)&Vs[s * 64 + m0];
            float va[4] = {vv.x, vv.y, vv.z, vv.w};
#pragma unroll
            for (int i = 0; i < 8; i++) {
                float sv = Ss[(t0 + i) * 128 + s];
#pragma unroll
                for (int j = 0; j < 4; j++) acc[i][j] += sv * va[j];
            }
        }
        for (int dd = 0; dd < DH; dd++) {
            float4 kv = *(const float4*)&KVp[dd * 64 + m0];
            float ka[4] = {kv.x, kv.y, kv.z, kv.w};
#pragma unroll
            for (int i = 0; i < 8; i++) {
                float qv = Qs[(t0 + i) * 64 + dd];
#pragma unroll
                for (int j = 0; j < 4; j++) acc[i][j] += qv * ka[j];
            }
        }
#pragma unroll
        for (int i = 0; i < 8; i++) {
            float inv = 1.0f / den[t0 + i];
            size_t ob = ((size_t)b * SEQ + (size_t)c * CHUNK + t0 + i) * DIM + h * 64 + m0;
            attn[ob + 0] = acc[i][0] * inv;
            attn[ob + 1] = acc[i][1] * inv;
            attn[ob + 2] = acc[i][2] * inv;
            attn[ob + 3] = acc[i][3] * inv;
        }
    }
}

// ---------------- host launch ----------------
extern "C" void kernel_launch(void* const* d_in, const int* in_sizes, int n_in,
                              void* d_out, int out_size) {
    const float* x    = (const float*)d_in[0];
    const float* wqkv = (const float*)d_in[1];
    const float* wout = (const float*)d_in[2];
    float* out = (float*)d_out;

    float *qkv, *qf, *kf, *v, *attn, *kvch, *ksch;
    cudaGetSymbolAddress((void**)&qkv,  g_qkv);
    cudaGetSymbolAddress((void**)&qf,   g_qf);
    cudaGetSymbolAddress((void**)&kf,   g_kf);
    cudaGetSymbolAddress((void**)&v,    g_v);
    cudaGetSymbolAddress((void**)&attn, g_attn);
    cudaGetSymbolAddress((void**)&kvch, g_kvch);
    cudaGetSymbolAddress((void**)&ksch, g_ksch);

    const size_t smemA = 2 * 8192 * sizeof(float);                       // 64 KB
    const size_t smemC = (8192 + 8448 + 8192 + 16384 + 4096 + 64 + 128 + 2048) * sizeof(float); // ~186 KB
    cudaFuncSetAttribute(chunk_sums_kernel, cudaFuncAttributeMaxDynamicSharedMemorySize, (int)smemA);
    cudaFuncSetAttribute(chunk_out_kernel,  cudaFuncAttributeMaxDynamicSharedMemorySize, (int)smemC);

    // 1) qkv = x @ w_qkv   (M=16384, N=3072, K=1024)
    sgemm128<<<dim3(3072 / 128, 16384 / 128), 256>>>(x, wqkv, qkv, BATCH * SEQ, 3 * DIM, DIM);
    // 2) RoPE + elu feature + transpose to [bh][n][64]
    featurize_kernel<<<(BATCH * SEQ * HEADS * 32) / 256, 256>>>(qkv, qf, kf, v);
    // 3) per-chunk K^T V sums
    chunk_sums_kernel<<<BH * NCHUNK, 256, smemA>>>(kf, v, kvch, ksch);
    // 4) exclusive prefix across chunks
    prefix_kernel<<<BH, 256>>>(kvch, ksch);
    // 5) per-chunk outputs
    chunk_out_kernel<<<BH * NCHUNK, 256, smemC>>>(qf, kf, v, kvch, ksch, attn);
    // 6) final = attn @ w_out   (M=16384, N=1024, K=1024)
    sgemm128<<<dim3(1024 / 128, 16384 / 128), 256>>>(attn, wout, out, BATCH * SEQ, DIM, DIM);
}

// round 2
// speedup vs baseline: 2.1141x; 2.1141x over previous
#include <cuda_runtime.h>
#include <math.h>
#include <stdint.h>

#define BATCH 4
#define SEQ   4096
#define DIM   1024
#define HEADS 16
#define DH    64
#define CHUNK 128
#define NCHUNK 32
#define BH    (BATCH*HEADS)
#define FEAT_SCALE 0.35355339059327373f  // 64^-0.25

// ---------------- scratch (device globals; no allocation allowed) ----------------
__device__ float g_qkv  [BATCH*SEQ*3*DIM];    // raw qkv (fp32 results of GEMM1)
__device__ float g_xr   [BATCH*SEQ*DIM];      // tf32-rounded x
__device__ float g_wqkvr[DIM*3*DIM];          // tf32-rounded w_qkv
__device__ float g_woutr[DIM*DIM];            // tf32-rounded w_out
__device__ float g_qf  [BH*SEQ*DH];
__device__ float g_kf  [BH*SEQ*DH];
__device__ float g_v   [BH*SEQ*DH];
__device__ float g_attn[BATCH*SEQ*DIM];       // attention out, tf32-rounded
__device__ float g_kvch[BH*NCHUNK*DH*DH];
__device__ float g_ksch[BH*NCHUNK*DH];

// ---------------- helpers ----------------
__device__ __forceinline__ float tf32r(float x) {
    uint32_t u;
    asm("cvt.rna.tf32.f32 %0, %1;" : "=r"(u) : "f"(x));
    return __uint_as_float(u);
}
__device__ __forceinline__ void cpasync16(void* dst, const void* src) {
    unsigned d = (unsigned)__cvta_generic_to_shared(dst);
    asm volatile("cp.async.ca.shared.global [%0], [%1], 16;" :: "r"(d), "l"(src));
}
#define CP_COMMIT()  asm volatile("cp.async.commit_group;")
#define CP_WAIT1()   asm volatile("cp.async.wait_group 1;")
#define CP_WAIT0()   asm volatile("cp.async.wait_group 0;")

// accurate sincos (immune to --use_fast_math)
__device__ __forceinline__ void rope_sincos(float ang, float& s, float& c) {
    double a  = (double)ang;
    double qd = floor(a * 0.63661977236758134 + 0.5);
    double r  = a - qd * 1.5707963267948966;
    float rf = (float)r;
    int qi = ((int)qd) & 3;
    float r2 = rf * rf;
    float sp = rf * (1.0f + r2 * (-1.6666667e-1f + r2 * (8.3333337e-3f
              + r2 * (-1.9841270e-4f + r2 * 2.7557319e-6f))));
    float cp = 1.0f + r2 * (-0.5f + r2 * (4.1666668e-2f
              + r2 * (-1.3888889e-3f + r2 * 2.4801587e-5f)));
    switch (qi) {
        case 0:  s =  sp; c =  cp; break;
        case 1:  s =  cp; c = -sp; break;
        case 2:  s = -sp; c = -cp; break;
        default: s = -cp; c =  sp; break;
    }
}

// ---------------- tf32 rounding pre-pass ----------------
__global__ void round_tf32_kernel(const float4* __restrict__ in, float4* __restrict__ out, int n4) {
    int i = blockIdx.x * blockDim.x + threadIdx.x;
    if (i < n4) {
        float4 v = in[i];
        v.x = tf32r(v.x); v.y = tf32r(v.y); v.z = tf32r(v.z); v.w = tf32r(v.w);
        out[i] = v;
    }
}

// ---------------- tf32 tensor-core GEMM: C[M,Nn] = A[M,K] @ B[K,Nn] (row-major) ----------------
// Block 128x128, BK=32, 256 threads (8 warps, 2x4), warp tile 64x32.
// A/B must be pre-rounded to tf32 bit patterns. fp32 accumulate.
__global__ void gemm_tf32(const float* __restrict__ A, const float* __restrict__ B,
                          float* __restrict__ C, int M, int Nn, int K) {
    extern __shared__ float sm[];
    // buffer layout: As (128x36) then Bs (32x136); two buffers
    const int AS_F = 128 * 36;   // 4608
    const int BS_F = 32 * 136;   // 4352
    const int BUF_F = AS_F + BS_F;  // 8960

    const int tid = threadIdx.x;
    const int bx = blockIdx.x, by = blockIdx.y;
    const int warp = tid >> 5, lane = tid & 31;
    const int gid = lane >> 2, tig = lane & 3;
    const int warpM = warp & 1, warpN = warp >> 1;
    const int mBase = warpM * 64;
    const int nBase = warpN * 32;

    const float* Ab = A + (size_t)(by * 128) * K;
    const float* Bb = B + (size_t)(bx * 128);

    float acc[4][4][4];
#pragma unroll
    for (int mi = 0; mi < 4; mi++)
#pragma unroll
        for (int nj = 0; nj < 4; nj++)
#pragma unroll
            for (int r = 0; r < 4; r++) acc[mi][nj][r] = 0.0f;

    const int KT = K >> 5;

    // per-thread load coords
    const int am  = tid >> 1;               // 0..127 (2 chunks per row row-split below)
    const int akq = (tid & 1) * 16;         // unused variant; use linear scheme instead

    auto load_tile = [&](int kt, float* buf) {
        float* As = buf;
        float* Bs = buf + AS_F;
        int k0 = kt * 32;
#pragma unroll
        for (int i = 0; i < 4; i++) {
            int lin = i * 256 + tid;        // 0..1023
            int m = lin >> 3;               // 0..127
            int kq = (lin & 7) * 4;         // 0..28
            cpasync16(&As[m * 36 + kq], Ab + (size_t)m * K + k0 + kq);
        }
#pragma unroll
        for (int i = 0; i < 4; i++) {
            int lin = i * 256 + tid;
            int k = lin >> 5;               // 0..31
            int nq = (lin & 31) * 4;        // 0..124
            cpasync16(&Bs[k * 136 + nq], Bb + (size_t)(k0 + k) * Nn + nq);
        }
    };

    load_tile(0, sm);
    CP_COMMIT();

    for (int kt = 0; kt < KT; kt++) {
        if (kt + 1 < KT) {
            load_tile(kt + 1, sm + ((kt + 1) & 1) * BUF_F);
            CP_COMMIT();
            CP_WAIT1();
        } else {
            CP_WAIT0();
        }
        __syncthreads();

        const uint32_t* Au = (const uint32_t*)(sm + (kt & 1) * BUF_F);
        const uint32_t* Bu = (const uint32_t*)(sm + (kt & 1) * BUF_F + AS_F);

#pragma unroll
        for (int kk = 0; kk < 32; kk += 8) {
            uint32_t bf[4][2];
#pragma unroll
            for (int nj = 0; nj < 4; nj++) {
                int n = nBase + nj * 8 + gid;
                bf[nj][0] = Bu[(kk + tig) * 136 + n];
                bf[nj][1] = Bu[(kk + tig + 4) * 136 + n];
            }
            uint32_t af[4][4];
#pragma unroll
            for (int mi = 0; mi < 4; mi++) {
                int m = mBase + mi * 16 + gid;
                af[mi][0] = Au[m * 36 + kk + tig];
                af[mi][1] = Au[(m + 8) * 36 + kk + tig];
                af[mi][2] = Au[m * 36 + kk + tig + 4];
                af[mi][3] = Au[(m + 8) * 36 + kk + tig + 4];
            }
#pragma unroll
            for (int mi = 0; mi < 4; mi++)
#pragma unroll
                for (int nj = 0; nj < 4; nj++) {
                    asm volatile(
                        "mma.sync.aligned.m16n8k8.row.col.f32.tf32.tf32.f32 "
                        "{%0,%1,%2,%3}, {%4,%5,%6,%7}, {%8,%9}, {%0,%1,%2,%3};"
                        : "+f"(acc[mi][nj][0]), "+f"(acc[mi][nj][1]),
                          "+f"(acc[mi][nj][2]), "+f"(acc[mi][nj][3])
                        : "r"(af[mi][0]), "r"(af[mi][1]), "r"(af[mi][2]), "r"(af[mi][3]),
                          "r"(bf[nj][0]), "r"(bf[nj][1]));
                }
        }
        __syncthreads();
    }

    // epilogue
#pragma unroll
    for (int mi = 0; mi < 4; mi++) {
        int row = by * 128 + mBase + mi * 16 + gid;
#pragma unroll
        for (int nj = 0; nj < 4; nj++) {
            int col = bx * 128 + nBase + nj * 8 + tig * 2;
            *(float2*)(C + (size_t)row * Nn + col)       = make_float2(acc[mi][nj][0], acc[mi][nj][1]);
            *(float2*)(C + (size_t)(row + 8) * Nn + col) = make_float2(acc[mi][nj][2], acc[mi][nj][3]);
        }
    }
}

// ---------------- featurize: RoPE + elu(x*s)+1, transpose to [bh][n][64] ----------------
__global__ void featurize_kernel(const float* __restrict__ qkv,
                                 float* __restrict__ qf, float* __restrict__ kf,
                                 float* __restrict__ v) {
    int idx = blockIdx.x * blockDim.x + threadIdx.x;
    int d = idx & 31;
    int h = (idx >> 5) & 15;
    int n = (idx >> 9) & 4095;
    int b = idx >> 21;

    size_t base = ((size_t)(b * SEQ + n)) * (3 * DIM);
    int col = h * 64 + d;
    float q1 = qkv[base + col],            q2 = qkv[base + col + 32];
    float k1 = qkv[base + DIM + col],      k2 = qkv[base + DIM + col + 32];
    float v1 = qkv[base + 2 * DIM + col],  v2 = qkv[base + 2 * DIM + col + 32];

    float inv_f = (float)exp(-(double)d * (9.210340371976184 / 32.0));
    float ang = (float)n * inv_f;
    float s, c;
    rope_sincos(ang, s, c);

    float qr1 = q1 * c - q2 * s, qr2 = q1 * s + q2 * c;
    float kr1 = k1 * c - k2 * s, kr2 = k1 * s + k2 * c;

    float yq1 = qr1 * FEAT_SCALE, yq2 = qr2 * FEAT_SCALE;
    float yk1 = kr1 * FEAT_SCALE, yk2 = kr2 * FEAT_SCALE;
    float fq1 = (yq1 > 0.0f) ? yq1 + 1.0f : expf(yq1);
    float fq2 = (yq2 > 0.0f) ? yq2 + 1.0f : expf(yq2);
    float fk1 = (yk1 > 0.0f) ? yk1 + 1.0f : expf(yk1);
    float fk2 = (yk2 > 0.0f) ? yk2 + 1.0f : expf(yk2);

    size_t obase = (((size_t)(b * HEADS + h)) * SEQ + n) * DH + d;
    qf[obase] = fq1; qf[obase + 32] = fq2;
    kf[obase] = fk1; kf[obase + 32] = fk2;
    v [obase] = v1;  v [obase + 32] = v2;
}

// ---------------- pass A: per-chunk K^T V (64x64) and sum(k) ----------------
__global__ void chunk_sums_kernel(const float* __restrict__ kf, const float* __restrict__ v,
                                  float* __restrict__ kvch, float* __restrict__ ksch) {
    extern __shared__ float sm[];
    float* Ks = sm;
    float* Vs = sm + 8192;

    int blk = blockIdx.x;
    int c  = blk % NCHUNK;
    int bh = blk / NCHUNK;
    int tid = threadIdx.x;

    size_t gbase = (((size_t)bh) * SEQ + (size_t)c * CHUNK) * DH;
    for (int i = tid; i < 2048; i += 256) {
        ((float4*)Ks)[i] = ((const float4*)(kf + gbase))[i];
        ((float4*)Vs)[i] = ((const float4*)(v  + gbase))[i];
    }
    __syncthreads();

    int i0 = (tid >> 4) * 4;
    int j0 = (tid & 15) * 4;
    float acc[4][4];
#pragma unroll
    for (int i = 0; i < 4; i++)
#pragma unroll
        for (int j = 0; j < 4; j++) acc[i][j] = 0.0f;

    for (int r = 0; r < CHUNK; r++) {
        float4 kv = *(const float4*)&Ks[r * 64 + i0];
        float4 vv = *(const float4*)&Vs[r * 64 + j0];
        float ka[4] = {kv.x, kv.y, kv.z, kv.w};
        float va[4] = {vv.x, vv.y, vv.z, vv.w};
#pragma unroll
        for (int i = 0; i < 4; i++)
#pragma unroll
            for (int j = 0; j < 4; j++) acc[i][j] += ka[i] * va[j];
    }

    size_t obase = ((size_t)bh * NCHUNK + c) * (DH * DH);
#pragma unroll
    for (int i = 0; i < 4; i++)
        *(float4*)&kvch[obase + (size_t)(i0 + i) * 64 + j0] =
            make_float4(acc[i][0], acc[i][1], acc[i][2], acc[i][3]);

    if (tid < 64) {
        float ssum = 0.0f;
        for (int r = 0; r < CHUNK; r++) ssum += Ks[r * 64 + tid];
        ksch[((size_t)bh * NCHUNK + c) * DH + tid] = ssum;
    }
}

// ---------------- pass B: exclusive prefix over chunks (in place) ----------------
__global__ void prefix_kernel(float* __restrict__ kvch, float* __restrict__ ksch) {
    int bh = blockIdx.x;
    for (int e = threadIdx.x; e < DH * DH; e += blockDim.x) {
        float acc = 0.0f;
        for (int c = 0; c < NCHUNK; c++) {
            float* p = &kvch[((size_t)bh * NCHUNK + c) * (DH * DH) + e];
            float t = *p; *p = acc; acc += t;
        }
    }
    for (int e = threadIdx.x; e < DH; e += blockDim.x) {
        float acc = 0.0f;
        for (int c = 0; c < NCHUNK; c++) {
            float* p = &ksch[((size_t)bh * NCHUNK + c) * DH + e];
            float t = *p; *p = acc; acc += t;
        }
    }
}

// ---------------- pass C: per-chunk output (stores attn tf32-rounded) ----------------
__global__ void chunk_out_kernel(const float* __restrict__ qf, const float* __restrict__ kf,
                                 const float* __restrict__ v, const float* __restrict__ kvch,
                                 const float* __restrict__ ksch, float* __restrict__ attn) {
    extern __shared__ float sm[];
    float* Qs   = sm;                       // 8192
    float* KsT  = Qs + 8192;                // 8448 (pitch 132)
    float* Vs   = KsT + 8448;               // 8192
    float* Ss   = Vs + 8192;                // 16384
    float* KVp  = Ss + 16384;               // 4096
    float* KSp  = KVp + 4096;               // 64
    float* den  = KSp + 64;                 // 128
    float* denp = den + 128;                // 2048

    int blk = blockIdx.x;
    int c  = blk % NCHUNK;
    int bh = blk / NCHUNK;
    int b  = bh / HEADS;
    int h  = bh % HEADS;
    int tid = threadIdx.x;

    size_t gbase = (((size_t)bh) * SEQ + (size_t)c * CHUNK) * DH;
    for (int i = tid; i < 2048; i += 256) {
        ((float4*)Qs)[i] = ((const float4*)(qf + gbase))[i];
        ((float4*)Vs)[i] = ((const float4*)(v  + gbase))[i];
        float4 kq = ((const float4*)(kf + gbase))[i];
        int r  = i >> 4;
        int c4 = (i & 15) * 4;
        KsT[(c4 + 0) * 132 + r] = kq.x;
        KsT[(c4 + 1) * 132 + r] = kq.y;
        KsT[(c4 + 2) * 132 + r] = kq.z;
        KsT[(c4 + 3) * 132 + r] = kq.w;
    }
    {
        size_t kvbase = ((size_t)bh * NCHUNK + c) * (DH * DH);
        for (int i = tid; i < 1024; i += 256)
            ((float4*)KVp)[i] = ((const float4*)(kvch + kvbase))[i];
        if (tid < 64)
            KSp[tid] = ksch[((size_t)bh * NCHUNK + c) * DH + tid];
    }
    __syncthreads();

    int ti = tid >> 4, tj = tid & 15;
    int t0 = ti * 8, s0 = tj * 8;
    {
        float acc[8][8];
#pragma unroll
        for (int i = 0; i < 8; i++)
#pragma unroll
            for (int j = 0; j < 8; j++) acc[i][j] = 0.0f;

        for (int dd = 0; dd < DH; dd++) {
            float ra[8], rb[8];
#pragma unroll
            for (int i = 0; i < 8; i++) ra[i] = Qs[(t0 + i) * 64 + dd];
            *(float4*)&rb[0] = *(const float4*)&KsT[dd * 132 + s0];
            *(float4*)&rb[4] = *(const float4*)&KsT[dd * 132 + s0 + 4];
#pragma unroll
            for (int i = 0; i < 8; i++)
#pragma unroll
                for (int j = 0; j < 8; j++) acc[i][j] += ra[i] * rb[j];
        }
#pragma unroll
        for (int i = 0; i < 8; i++) {
            float rsum = 0.0f;
#pragma unroll
            for (int j = 0; j < 8; j++) {
                float val = (s0 + j <= t0 + i) ? acc[i][j] : 0.0f;
                acc[i][j] = val;
                rsum += val;
            }
            denp[(t0 + i) * 16 + tj] = rsum;
            *(float4*)&Ss[(t0 + i) * 128 + s0]     = make_float4(acc[i][0], acc[i][1], acc[i][2], acc[i][3]);
            *(float4*)&Ss[(t0 + i) * 128 + s0 + 4] = make_float4(acc[i][4], acc[i][5], acc[i][6], acc[i][7]);
        }
    }
    __syncthreads();

    if (tid < 128) {
        float dsum = 0.0f;
#pragma unroll
        for (int j = 0; j < 16; j++) dsum += denp[tid * 16 + j];
        for (int dd = 0; dd < DH; dd++) dsum += Qs[tid * 64 + dd] * KSp[dd];
        den[tid] = fmaxf(dsum, 1e-6f);
    }
    __syncthreads();

    {
        int m0 = tj * 4;
        float acc[8][4];
#pragma unroll
        for (int i = 0; i < 8; i++)
#pragma unroll
            for (int j = 0; j < 4; j++) acc[i][j] = 0.0f;

        for (int s = 0; s < CHUNK; s++) {
            float4 vv = *(const float4*)&Vs[s * 64 + m0];
            float va[4] = {vv.x, vv.y, vv.z, vv.w};
#pragma unroll
            for (int i = 0; i < 8; i++) {
                float sv = Ss[(t0 + i) * 128 + s];
#pragma unroll
                for (int j = 0; j < 4; j++) acc[i][j] += sv * va[j];
            }
        }
        for (int dd = 0; dd < DH; dd++) {
            float4 kv = *(const float4*)&KVp[dd * 64 + m0];
            float ka[4] = {kv.x, kv.y, kv.z, kv.w};
#pragma unroll
            for (int i = 0; i < 8; i++) {
                float qv = Qs[(t0 + i) * 64 + dd];
#pragma unroll
                for (int j = 0; j < 4; j++) acc[i][j] += qv * ka[j];
            }
        }
#pragma unroll
        for (int i = 0; i < 8; i++) {
            float inv = 1.0f / den[t0 + i];
            size_t ob = ((size_t)b * SEQ + (size_t)c * CHUNK + t0 + i) * DIM + h * 64 + m0;
            attn[ob + 0] = tf32r(acc[i][0] * inv);
            attn[ob + 1] = tf32r(acc[i][1] * inv);
            attn[ob + 2] = tf32r(acc[i][2] * inv);
            attn[ob + 3] = tf32r(acc[i][3] * inv);
        }
    }
}

// ---------------- host launch ----------------
extern "C" void kernel_launch(void* const* d_in, const int* in_sizes, int n_in,
                              void* d_out, int out_size) {
    const float* x    = (const float*)d_in[0];
    const float* wqkv = (const float*)d_in[1];
    const float* wout = (const float*)d_in[2];
    float* out = (float*)d_out;

    float *qkv, *xr, *wqkvr, *woutr, *qf, *kf, *v, *attn, *kvch, *ksch;
    cudaGetSymbolAddress((void**)&qkv,   g_qkv);
    cudaGetSymbolAddress((void**)&xr,    g_xr);
    cudaGetSymbolAddress((void**)&wqkvr, g_wqkvr);
    cudaGetSymbolAddress((void**)&woutr, g_woutr);
    cudaGetSymbolAddress((void**)&qf,    g_qf);
    cudaGetSymbolAddress((void**)&kf,    g_kf);
    cudaGetSymbolAddress((void**)&v,     g_v);
    cudaGetSymbolAddress((void**)&attn,  g_attn);
    cudaGetSymbolAddress((void**)&kvch,  g_kvch);
    cudaGetSymbolAddress((void**)&ksch,  g_ksch);

    const size_t smemG = 2 * (128 * 36 + 32 * 136) * sizeof(float);      // 71680 B
    const size_t smemA = 2 * 8192 * sizeof(float);
    const size_t smemC = (8192 + 8448 + 8192 + 16384 + 4096 + 64 + 128 + 2048) * sizeof(float);
    cudaFuncSetAttribute(gemm_tf32,         cudaFuncAttributeMaxDynamicSharedMemorySize, (int)smemG);
    cudaFuncSetAttribute(chunk_sums_kernel, cudaFuncAttributeMaxDynamicSharedMemorySize, (int)smemA);
    cudaFuncSetAttribute(chunk_out_kernel,  cudaFuncAttributeMaxDynamicSharedMemorySize, (int)smemC);

    // 0) tf32-round inputs
    {
        int n4x = (BATCH * SEQ * DIM) / 4;
        int n4w = (DIM * 3 * DIM) / 4;
        int n4o = (DIM * DIM) / 4;
        round_tf32_kernel<<<(n4x + 255) / 256, 256>>>((const float4*)x,    (float4*)xr,    n4x);
        round_tf32_kernel<<<(n4w + 255) / 256, 256>>>((const float4*)wqkv, (float4*)wqkvr, n4w);
        round_tf32_kernel<<<(n4o + 255) / 256, 256>>>((const float4*)wout, (float4*)woutr, n4o);
    }

    // 1) qkv = xr @ wqkvr   (M=16384, N=3072, K=1024)  [tensor cores, tf32]
    gemm_tf32<<<dim3(3072 / 128, 16384 / 128), 256, smemG>>>(xr, wqkvr, qkv, BATCH * SEQ, 3 * DIM, DIM);
    // 2) RoPE + elu feature + transpose
    featurize_kernel<<<(BATCH * SEQ * HEADS * 32) / 256, 256>>>(qkv, qf, kf, v);
    // 3) per-chunk K^T V sums
    chunk_sums_kernel<<<BH * NCHUNK, 256, smemA>>>(kf, v, kvch, ksch);
    // 4) exclusive prefix across chunks
    prefix_kernel<<<BH, 1024>>>(kvch, ksch);
    // 5) per-chunk outputs (attn stored tf32-rounded)
    chunk_out_kernel<<<BH * NCHUNK, 256, smemC>>>(qf, kf, v, kvch, ksch, attn);
    // 6) final = attn @ woutr   (M=16384, N=1024, K=1024)  [tensor cores, tf32]
    gemm_tf32<<<dim3(1024 / 128, 16384 / 128), 256, smemG>>>(attn, woutr, out, BATCH * SEQ, DIM, DIM);
}

// round 3
// speedup vs baseline: 2.1533x; 1.0185x over previous
#include <cuda_runtime.h>
#include <math.h>
#include <stdint.h>

#define BATCH 4
#define SEQ   4096
#define DIM   1024
#define HEADS 16
#define DH    64
#define CHUNK 128
#define NCHUNK 32
#define BH    (BATCH*HEADS)
#define FEAT_SCALE 0.35355339059327373f  // 64^-0.25

// ---------------- scratch (device globals; no allocation allowed) ----------------
__device__ float g_qkv  [BATCH*SEQ*3*DIM];
__device__ float g_xr   [BATCH*SEQ*DIM];
__device__ float g_wqkvr[DIM*3*DIM];
__device__ float g_woutr[DIM*DIM];
__device__ float g_qf  [BH*SEQ*DH];
__device__ float g_kf  [BH*SEQ*DH];
__device__ float g_v   [BH*SEQ*DH];
__device__ float g_attn[BATCH*SEQ*DIM];
__device__ float g_kvch[BH*NCHUNK*DH*DH];
__device__ float g_ksch[BH*NCHUNK*DH];

// ---------------- helpers ----------------
__device__ __forceinline__ float tf32r(float x) {
    uint32_t u;
    asm("cvt.rna.tf32.f32 %0, %1;" : "=r"(u) : "f"(x));
    return __uint_as_float(u);
}
__device__ __forceinline__ void cpasync16(void* dst, const void* src) {
    unsigned d = (unsigned)__cvta_generic_to_shared(dst);
    asm volatile("cp.async.ca.shared.global [%0], [%1], 16;" :: "r"(d), "l"(src));
}
#define CP_COMMIT()  asm volatile("cp.async.commit_group;")
#define CP_WAIT1()   asm volatile("cp.async.wait_group 1;")

// accurate sincos (immune to --use_fast_math)
__device__ __forceinline__ void rope_sincos(float ang, float& s, float& c) {
    double a  = (double)ang;
    double qd = floor(a * 0.63661977236758134 + 0.5);
    double r  = a - qd * 1.5707963267948966;
    float rf = (float)r;
    int qi = ((int)qd) & 3;
    float r2 = rf * rf;
    float sp = rf * (1.0f + r2 * (-1.6666667e-1f + r2 * (8.3333337e-3f
              + r2 * (-1.9841270e-4f + r2 * 2.7557319e-6f))));
    float cp = 1.0f + r2 * (-0.5f + r2 * (4.1666668e-2f
              + r2 * (-1.3888889e-3f + r2 * 2.4801587e-5f)));
    switch (qi) {
        case 0:  s =  sp; c =  cp; break;
        case 1:  s =  cp; c = -sp; break;
        case 2:  s = -sp; c = -cp; break;
        default: s = -cp; c =  sp; break;
    }
}

// ---------------- tf32 rounding pre-pass ----------------
__global__ void round_tf32_kernel(const float4* __restrict__ in, float4* __restrict__ out, int n4) {
    int i = blockIdx.x * blockDim.x + threadIdx.x;
    if (i < n4) {
        float4 v = in[i];
        v.x = tf32r(v.x); v.y = tf32r(v.y); v.z = tf32r(v.z); v.w = tf32r(v.w);
        out[i] = v;
    }
}

// ---------------- tf32 tensor-core GEMM ----------------
// Block 128x128, BK=32, 3-stage cp.async pipeline, 256 threads (8 warps 2x4),
// warp tile 64x32, register double-buffered fragments. fp32 accumulate.
__global__ __launch_bounds__(256) void gemm_tf32(
        const float* __restrict__ A, const float* __restrict__ B,
        float* __restrict__ C, int M, int Nn, int K) {
    extern __shared__ float sm[];
    const int AS_F = 128 * 36;      // 4608
    const int BS_F = 32 * 136;      // 4352
    const int BUF_F = AS_F + BS_F;  // 8960 floats per stage

    const int tid = threadIdx.x;
    const int bx = blockIdx.x, by = blockIdx.y;
    const int warp = tid >> 5, lane = tid & 31;
    const int gid = lane >> 2, tig = lane & 3;
    const int warpM = warp & 1, warpN = warp >> 1;
    const int mBase = warpM * 64;
    const int nBase = warpN * 32;

    const float* Ab = A + (size_t)(by * 128) * K;
    const float* Bb = B + (size_t)(bx * 128);

    float acc[4][4][4];
#pragma unroll
    for (int mi = 0; mi < 4; mi++)
#pragma unroll
        for (int nj = 0; nj < 4; nj++)
#pragma unroll
            for (int r = 0; r < 4; r++) acc[mi][nj][r] = 0.0f;

    const int KT = K >> 5;

    auto load_tile = [&](int kt, float* buf) {
        float* As = buf;
        float* Bs = buf + AS_F;
        int k0 = kt * 32;
#pragma unroll
        for (int i = 0; i < 4; i++) {
            int lin = i * 256 + tid;
            int m = lin >> 3;
            int kq = (lin & 7) * 4;
            cpasync16(&As[m * 36 + kq], Ab + (size_t)m * K + k0 + kq);
        }
#pragma unroll
        for (int i = 0; i < 4; i++) {
            int lin = i * 256 + tid;
            int k = lin >> 5;
            int nq = (lin & 31) * 4;
            cpasync16(&Bs[k * 136 + nq], Bb + (size_t)(k0 + k) * Nn + nq);
        }
    };

    // prologue: stages 0 and 1
    load_tile(0, sm);
    CP_COMMIT();
    load_tile(1, sm + BUF_F);
    CP_COMMIT();

    uint32_t af[2][4][4];
    uint32_t bf[2][4][2];

    for (int kt = 0; kt < KT; kt++) {
        CP_WAIT1();                 // stage kt resident
        __syncthreads();

        // issue loads for stage kt+2 (buffer reuse safe: all warps finished kt-1)
        if (kt + 2 < KT) load_tile(kt + 2, sm + ((kt + 2) % 3) * BUF_F);
        CP_COMMIT();                // commit (possibly empty) keeps group counting uniform

        const uint32_t* Au = (const uint32_t*)(sm + (kt % 3) * BUF_F);
        const uint32_t* Bu = (const uint32_t*)(sm + (kt % 3) * BUF_F + AS_F);

        // preload fragments of slice 0
#pragma unroll
        for (int nj = 0; nj < 4; nj++) {
            int n = nBase + nj * 8 + gid;
            bf[0][nj][0] = Bu[tig * 136 + n];
            bf[0][nj][1] = Bu[(tig + 4) * 136 + n];
        }
#pragma unroll
        for (int mi = 0; mi < 4; mi++) {
            int m = mBase + mi * 16 + gid;
            af[0][mi][0] = Au[m * 36 + tig];
            af[0][mi][1] = Au[(m + 8) * 36 + tig];
            af[0][mi][2] = Au[m * 36 + tig + 4];
            af[0][mi][3] = Au[(m + 8) * 36 + tig + 4];
        }

#pragma unroll
        for (int s = 0; s < 4; s++) {
            int cur = s & 1, nxt = cur ^ 1;
            if (s < 3) {
                int kk = (s + 1) * 8;
#pragma unroll
                for (int nj = 0; nj < 4; nj++) {
                    int n = nBase + nj * 8 + gid;
                    bf[nxt][nj][0] = Bu[(kk + tig) * 136 + n];
                    bf[nxt][nj][1] = Bu[(kk + tig + 4) * 136 + n];
                }
#pragma unroll
                for (int mi = 0; mi < 4; mi++) {
                    int m = mBase + mi * 16 + gid;
                    af[nxt][mi][0] = Au[m * 36 + kk + tig];
                    af[nxt][mi][1] = Au[(m + 8) * 36 + kk + tig];
                    af[nxt][mi][2] = Au[m * 36 + kk + tig + 4];
                    af[nxt][mi][3] = Au[(m + 8) * 36 + kk + tig + 4];
                }
            }
#pragma unroll
            for (int mi = 0; mi < 4; mi++)
#pragma unroll
                for (int nj = 0; nj < 4; nj++) {
                    asm volatile(
                        "mma.sync.aligned.m16n8k8.row.col.f32.tf32.tf32.f32 "
                        "{%0,%1,%2,%3}, {%4,%5,%6,%7}, {%8,%9}, {%0,%1,%2,%3};"
                        : "+f"(acc[mi][nj][0]), "+f"(acc[mi][nj][1]),
                          "+f"(acc[mi][nj][2]), "+f"(acc[mi][nj][3])
                        : "r"(af[cur][mi][0]), "r"(af[cur][mi][1]),
                          "r"(af[cur][mi][2]), "r"(af[cur][mi][3]),
                          "r"(bf[cur][nj][0]), "r"(bf[cur][nj][1]));
                }
        }
        __syncthreads();
    }

    // epilogue
#pragma unroll
    for (int mi = 0; mi < 4; mi++) {
        int row = by * 128 + mBase + mi * 16 + gid;
#pragma unroll
        for (int nj = 0; nj < 4; nj++) {
            int col = bx * 128 + nBase + nj * 8 + tig * 2;
            *(float2*)(C + (size_t)row * Nn + col)       = make_float2(acc[mi][nj][0], acc[mi][nj][1]);
            *(float2*)(C + (size_t)(row + 8) * Nn + col) = make_float2(acc[mi][nj][2], acc[mi][nj][3]);
        }
    }
}

// ---------------- featurize: RoPE + elu(x*s)+1, transpose to [bh][n][64] ----------------
__global__ void featurize_kernel(const float* __restrict__ qkv,
                                 float* __restrict__ qf, float* __restrict__ kf,
                                 float* __restrict__ v) {
    int idx = blockIdx.x * blockDim.x + threadIdx.x;
    int d = idx & 31;
    int h = (idx >> 5) & 15;
    int n = (idx >> 9) & 4095;
    int b = idx >> 21;

    size_t base = ((size_t)(b * SEQ + n)) * (3 * DIM);
    int col = h * 64 + d;
    float q1 = qkv[base + col],            q2 = qkv[base + col + 32];
    float k1 = qkv[base + DIM + col],      k2 = qkv[base + DIM + col + 32];
    float v1 = qkv[base + 2 * DIM + col],  v2 = qkv[base + 2 * DIM + col + 32];

    float inv_f = (float)exp(-(double)d * (9.210340371976184 / 32.0));
    float ang = (float)n * inv_f;
    float s, c;
    rope_sincos(ang, s, c);

    float qr1 = q1 * c - q2 * s, qr2 = q1 * s + q2 * c;
    float kr1 = k1 * c - k2 * s, kr2 = k1 * s + k2 * c;

    float yq1 = qr1 * FEAT_SCALE, yq2 = qr2 * FEAT_SCALE;
    float yk1 = kr1 * FEAT_SCALE, yk2 = kr2 * FEAT_SCALE;
    float fq1 = (yq1 > 0.0f) ? yq1 + 1.0f : expf(yq1);
    float fq2 = (yq2 > 0.0f) ? yq2 + 1.0f : expf(yq2);
    float fk1 = (yk1 > 0.0f) ? yk1 + 1.0f : expf(yk1);
    float fk2 = (yk2 > 0.0f) ? yk2 + 1.0f : expf(yk2);

    size_t obase = (((size_t)(b * HEADS + h)) * SEQ + n) * DH + d;
    qf[obase] = fq1; qf[obase + 32] = fq2;
    kf[obase] = fk1; kf[obase + 32] = fk2;
    v [obase] = v1;  v [obase + 32] = v2;
}

// ---------------- pass A: per-chunk K^T V (64x64) and sum(k) ----------------
__global__ void chunk_sums_kernel(const float* __restrict__ kf, const float* __restrict__ v,
                                  float* __restrict__ kvch, float* __restrict__ ksch) {
    extern __shared__ float sm[];
    float* Ks = sm;
    float* Vs = sm + 8192;

    int blk = blockIdx.x;
    int c  = blk % NCHUNK;
    int bh = blk / NCHUNK;
    int tid = threadIdx.x;

    size_t gbase = (((size_t)bh) * SEQ + (size_t)c * CHUNK) * DH;
    for (int i = tid; i < 2048; i += 256) {
        ((float4*)Ks)[i] = ((const float4*)(kf + gbase))[i];
        ((float4*)Vs)[i] = ((const float4*)(v  + gbase))[i];
    }
    __syncthreads();

    int i0 = (tid >> 4) * 4;
    int j0 = (tid & 15) * 4;
    float acc[4][4];
#pragma unroll
    for (int i = 0; i < 4; i++)
#pragma unroll
        for (int j = 0; j < 4; j++) acc[i][j] = 0.0f;

    for (int r = 0; r < CHUNK; r++) {
        float4 kv = *(const float4*)&Ks[r * 64 + i0];
        float4 vv = *(const float4*)&Vs[r * 64 + j0];
        float ka[4] = {kv.x, kv.y, kv.z, kv.w};
        float va[4] = {vv.x, vv.y, vv.z, vv.w};
#pragma unroll
        for (int i = 0; i < 4; i++)
#pragma unroll
            for (int j = 0; j < 4; j++) acc[i][j] += ka[i] * va[j];
    }

    size_t obase = ((size_t)bh * NCHUNK + c) * (DH * DH);
#pragma unroll
    for (int i = 0; i < 4; i++)
        *(float4*)&kvch[obase + (size_t)(i0 + i) * 64 + j0] =
            make_float4(acc[i][0], acc[i][1], acc[i][2], acc[i][3]);

    if (tid < 64) {
        float ssum = 0.0f;
        for (int r = 0; r < CHUNK; r++) ssum += Ks[r * 64 + tid];
        ksch[((size_t)bh * NCHUNK + c) * DH + tid] = ssum;
    }
}

// ---------------- pass B: exclusive prefix over chunks (in place) ----------------
__global__ void prefix_kernel(float* __restrict__ kvch, float* __restrict__ ksch) {
    int bh = blockIdx.x;
    for (int e = threadIdx.x; e < DH * DH; e += blockDim.x) {
        float acc = 0.0f;
        for (int c = 0; c < NCHUNK; c++) {
            float* p = &kvch[((size_t)bh * NCHUNK + c) * (DH * DH) + e];
            float t = *p; *p = acc; acc += t;
        }
    }
    for (int e = threadIdx.x; e < DH; e += blockDim.x) {
        float acc = 0.0f;
        for (int c = 0; c < NCHUNK; c++) {
            float* p = &ksch[((size_t)bh * NCHUNK + c) * DH + e];
            float t = *p; *p = acc; acc += t;
        }
    }
}

// ---------------- pass C: per-chunk output (stores attn tf32-rounded) ----------------
__global__ void chunk_out_kernel(const float* __restrict__ qf, const float* __restrict__ kf,
                                 const float* __restrict__ v, const float* __restrict__ kvch,
                                 const float* __restrict__ ksch, float* __restrict__ attn) {
    extern __shared__ float sm[];
    float* Qs   = sm;                       // 8192
    float* KsT  = Qs + 8192;                // 8448 (pitch 132)
    float* Vs   = KsT + 8448;               // 8192
    float* Ss   = Vs + 8192;                // 16384
    float* KVp  = Ss + 16384;               // 4096
    float* KSp  = KVp + 4096;               // 64
    float* den  = KSp + 64;                 // 128
    float* denp = den + 128;                // 2048

    int blk = blockIdx.x;
    int c  = blk % NCHUNK;
    int bh = blk / NCHUNK;
    int b  = bh / HEADS;
    int h  = bh % HEADS;
    int tid = threadIdx.x;

    size_t gbase = (((size_t)bh) * SEQ + (size_t)c * CHUNK) * DH;
    for (int i = tid; i < 2048; i += 256) {
        ((float4*)Qs)[i] = ((const float4*)(qf + gbase))[i];
        ((float4*)Vs)[i] = ((const float4*)(v  + gbase))[i];
        float4 kq = ((const float4*)(kf + gbase))[i];
        int r  = i >> 4;
        int c4 = (i & 15) * 4;
        KsT[(c4 + 0) * 132 + r] = kq.x;
        KsT[(c4 + 1) * 132 + r] = kq.y;
        KsT[(c4 + 2) * 132 + r] = kq.z;
        KsT[(c4 + 3) * 132 + r] = kq.w;
    }
    {
        size_t kvbase = ((size_t)bh * NCHUNK + c) * (DH * DH);
        for (int i = tid; i < 1024; i += 256)
            ((float4*)KVp)[i] = ((const float4*)(kvch + kvbase))[i];
        if (tid < 64)
            KSp[tid] = ksch[((size_t)bh * NCHUNK + c) * DH + tid];
    }
    __syncthreads();

    int ti = tid >> 4, tj = tid & 15;
    int t0 = ti * 8, s0 = tj * 8;
    {
        float acc[8][8];
#pragma unroll
        for (int i = 0; i < 8; i++)
#pragma unroll
            for (int j = 0; j < 8; j++) acc[i][j] = 0.0f;

        for (int dd = 0; dd < DH; dd++) {
            float ra[8], rb[8];
#pragma unroll
            for (int i = 0; i < 8; i++) ra[i] = Qs[(t0 + i) * 64 + dd];
            *(float4*)&rb[0] = *(const float4*)&KsT[dd * 132 + s0];
            *(float4*)&rb[4] = *(const float4*)&KsT[dd * 132 + s0 + 4];
#pragma unroll
            for (int i = 0; i < 8; i++)
#pragma unroll
                for (int j = 0; j < 8; j++) acc[i][j] += ra[i] * rb[j];
        }
#pragma unroll
        for (int i = 0; i < 8; i++) {
            float rsum = 0.0f;
#pragma unroll
            for (int j = 0; j < 8; j++) {
                float val = (s0 + j <= t0 + i) ? acc[i][j] : 0.0f;
                acc[i][j] = val;
                rsum += val;
            }
            denp[(t0 + i) * 16 + tj] = rsum;
            *(float4*)&Ss[(t0 + i) * 128 + s0]     = make_float4(acc[i][0], acc[i][1], acc[i][2], acc[i][3]);
            *(float4*)&Ss[(t0 + i) * 128 + s0 + 4] = make_float4(acc[i][4], acc[i][5], acc[i][6], acc[i][7]);
        }
    }
    __syncthreads();

    if (tid < 128) {
        float dsum = 0.0f;
#pragma unroll
        for (int j = 0; j < 16; j++) dsum += denp[tid * 16 + j];
        for (int dd = 0; dd < DH; dd++) dsum += Qs[tid * 64 + dd] * KSp[dd];
        den[tid] = fmaxf(dsum, 1e-6f);
    }
    __syncthreads();

    {
        int m0 = tj * 4;
        float acc[8][4];
#pragma unroll
        for (int i = 0; i < 8; i++)
#pragma unroll
            for (int j = 0; j < 4; j++) acc[i][j] = 0.0f;

        for (int s = 0; s < CHUNK; s++) {
            float4 vv = *(const float4*)&Vs[s * 64 + m0];
            float va[4] = {vv.x, vv.y, vv.z, vv.w};
#pragma unroll
            for (int i = 0; i < 8; i++) {
                float sv = Ss[(t0 + i) * 128 + s];
#pragma unroll
                for (int j = 0; j < 4; j++) acc[i][j] += sv * va[j];
            }
        }
        for (int dd = 0; dd < DH; dd++) {
            float4 kv = *(const float4*)&KVp[dd * 64 + m0];
            float ka[4] = {kv.x, kv.y, kv.z, kv.w};
#pragma unroll
            for (int i = 0; i < 8; i++) {
                float qv = Qs[(t0 + i) * 64 + dd];
#pragma unroll
                for (int j = 0; j < 4; j++) acc[i][j] += qv * ka[j];
            }
        }
#pragma unroll
        for (int i = 0; i < 8; i++) {
            float inv = 1.0f / den[t0 + i];
            size_t ob = ((size_t)b * SEQ + (size_t)c * CHUNK + t0 + i) * DIM + h * 64 + m0;
            attn[ob + 0] = tf32r(acc[i][0] * inv);
            attn[ob + 1] = tf32r(acc[i][1] * inv);
            attn[ob + 2] = tf32r(acc[i][2] * inv);
            attn[ob + 3] = tf32r(acc[i][3] * inv);
        }
    }
}

// ---------------- host launch ----------------
extern "C" void kernel_launch(void* const* d_in, const int* in_sizes, int n_in,
                              void* d_out, int out_size) {
    const float* x    = (const float*)d_in[0];
    const float* wqkv = (const float*)d_in[1];
    const float* wout = (const float*)d_in[2];
    float* out = (float*)d_out;

    float *qkv, *xr, *wqkvr, *woutr, *qf, *kf, *v, *attn, *kvch, *ksch;
    cudaGetSymbolAddress((void**)&qkv,   g_qkv);
    cudaGetSymbolAddress((void**)&xr,    g_xr);
    cudaGetSymbolAddress((void**)&wqkvr, g_wqkvr);
    cudaGetSymbolAddress((void**)&woutr, g_woutr);
    cudaGetSymbolAddress((void**)&qf,    g_qf);
    cudaGetSymbolAddress((void**)&kf,    g_kf);
    cudaGetSymbolAddress((void**)&v,     g_v);
    cudaGetSymbolAddress((void**)&attn,  g_attn);
    cudaGetSymbolAddress((void**)&kvch,  g_kvch);
    cudaGetSymbolAddress((void**)&ksch,  g_ksch);

    const size_t smemG = 3 * (128 * 36 + 32 * 136) * sizeof(float);      // 107520 B
    const size_t smemA = 2 * 8192 * sizeof(float);
    const size_t smemC = (8192 + 8448 + 8192 + 16384 + 4096 + 64 + 128 + 2048) * sizeof(float);
    cudaFuncSetAttribute(gemm_tf32,         cudaFuncAttributeMaxDynamicSharedMemorySize, (int)smemG);
    cudaFuncSetAttribute(chunk_sums_kernel, cudaFuncAttributeMaxDynamicSharedMemorySize, (int)smemA);
    cudaFuncSetAttribute(chunk_out_kernel,  cudaFuncAttributeMaxDynamicSharedMemorySize, (int)smemC);

    // 0) tf32-round inputs
    {
        int n4x = (BATCH * SEQ * DIM) / 4;
        int n4w = (DIM * 3 * DIM) / 4;
        int n4o = (DIM * DIM) / 4;
        round_tf32_kernel<<<(n4x + 255) / 256, 256>>>((const float4*)x,    (float4*)xr,    n4x);
        round_tf32_kernel<<<(n4w + 255) / 256, 256>>>((const float4*)wqkv, (float4*)wqkvr, n4w);
        round_tf32_kernel<<<(n4o + 255) / 256, 256>>>((const float4*)wout, (float4*)woutr, n4o);
    }

    // 1) qkv = xr @ wqkvr  (tensor cores, tf32, 3-stage pipeline)
    gemm_tf32<<<dim3(3072 / 128, 16384 / 128), 256, smemG>>>(xr, wqkvr, qkv, BATCH * SEQ, 3 * DIM, DIM);
    // 2) RoPE + elu feature + transpose
    featurize_kernel<<<(BATCH * SEQ * HEADS * 32) / 256, 256>>>(qkv, qf, kf, v);
    // 3) per-chunk K^T V sums
    chunk_sums_kernel<<<BH * NCHUNK, 256, smemA>>>(kf, v, kvch, ksch);
    // 4) exclusive prefix across chunks
    prefix_kernel<<<BH, 1024>>>(kvch, ksch);
    // 5) per-chunk outputs (attn stored tf32-rounded)
    chunk_out_kernel<<<BH * NCHUNK, 256, smemC>>>(qf, kf, v, kvch, ksch, attn);
    // 6) final = attn @ woutr
    gemm_tf32<<<dim3(1024 / 128, 16384 / 128), 256, smemG>>>(attn, woutr, out, BATCH * SEQ, DIM, DIM);
}